// round 15
// baseline (speedup 1.0000x reference)
#include <cuda_runtime.h>

// ============================================================================
// Connect_Loss: opening(cross) -> global minmax norm -> binarize(0.5)
//   -> 150 iters of fg-masked 3x3 maxpool label propagation (exact)
//   -> count distinct labels -> |ccsg - ccs| / numSg  (scalar out)
// Shapes: img, lab: (4,1,1024,1024) fp32. 8 slices of 1024^2 total.
//
// ASYNC persistent propagation: no global barrier between rounds. Each tile
// publishes ((done+1)<<20)|chg_bits with st.release; round r processing
// acquire-spins on the 9 cone neighbors' done>=r. Rounds pipeline as a
// wavefront; skipped tiles (no cone change last round) are provably fixed
// and identical in both ping-pong buffers. 18x8 + 6 = 150 steps, bit-exact.
// ============================================================================

#define NPIX  (8u << 20)            // 8,388,608 px total (2 tensors)

__device__ int   g_labA[NPIX];               // label ping (round 0,2,... output)
__device__ int   g_labB[NPIX];               // label pong; float scratch: opened img
__device__ unsigned int  g_red[4];           // mn0,mx0,mn1,mx1 as uint bits (nonneg)
__device__ unsigned int  g_cnt[4];           // distinct0, distinct1, numSg
__device__ unsigned int  g_zf[2];            // background-exists flags
__device__ unsigned int  g_bar_cnt;          // barrier arrival counter
__device__ unsigned int  g_bar_gen;          // barrier generation
__device__ unsigned int           g_tw[8][16][10];   // ((done+1)<<20)|chg_bits
__device__ unsigned long long     g_tsum[8][16][10]; // per-tile interior sums

__device__ __forceinline__ int max3i(int a, int b, int c) {
  return __vimax3_s32(a, b, c);
}
__device__ __forceinline__ unsigned ld_acq(const unsigned* p) {
  unsigned v;
  asm volatile("ld.acquire.gpu.global.b32 %0, [%1];" : "=r"(v) : "l"(p) : "memory");
  return v;
}
__device__ __forceinline__ void st_rel(unsigned* p, unsigned v) {
  asm volatile("st.release.gpu.global.b32 [%0], %1;" :: "l"(p), "r"(v) : "memory");
}

// ---------------------------------------------------------------------------
__global__ void k_init() {
  unsigned tid = threadIdx.x;
  unsigned* tw = &g_tw[0][0][0];
  for (unsigned i = tid; i < 8u * 16u * 10u; i += 256u) tw[i] = 0u;
  if (tid == 0) {
    g_red[0] = 0x7f800000u; g_red[1] = 0u;
    g_red[2] = 0x7f800000u; g_red[3] = 0u;
    g_cnt[0] = 0u; g_cnt[1] = 0u; g_cnt[2] = 0u; g_cnt[3] = 0u;
    g_zf[0] = 0u; g_zf[1] = 0u;
    g_bar_cnt = 0u;
  }
}

// ---------------------------------------------------------------------------
// fused opening in smem; stores opened float (into g_labB) + min/max reduce
// ---------------------------------------------------------------------------
#define OX 64
#define OY 16

__global__ void __launch_bounds__(256) k_open(const float* __restrict__ img,
                                              const float* __restrict__ lab) {
  __shared__ float RAW[OY + 4][OX + 4];
  __shared__ float ER[OY + 2][OX + 4];
  __shared__ float smn[8], smx[8];

  unsigned s = blockIdx.z;
  const float* __restrict__ p = (s < 4u) ? (img + (s << 20)) : (lab + ((s - 4u) << 20));
  float* __restrict__ op = ((float*)g_labB) + (s << 20);

  int gx0 = (int)blockIdx.x * OX - 2;
  int gy0 = (int)blockIdx.y * OY - 2;
  int tid = threadIdx.x;

  for (int i = tid; i < (OY + 4) * (OX + 4); i += 256) {
    int ly = i / (OX + 4), lx = i - ly * (OX + 4);
    int gy = gy0 + ly, gx = gx0 + lx;
    float v = 1e30f;
    if ((unsigned)gy < 1024u && (unsigned)gx < 1024u)
      v = p[((unsigned)gy << 10) + (unsigned)gx];
    RAW[ly][lx] = v;
  }
  __syncthreads();

  for (int i = tid; i < (OY + 2) * (OX + 2); i += 256) {
    int ey = i / (OX + 2), ex = i - ey * (OX + 2);
    int gy = gy0 + 1 + ey, gx = gx0 + 1 + ex;
    float v = -1e30f;
    if ((unsigned)gy < 1024u && (unsigned)gx < 1024u) {
      v = RAW[ey + 1][ex + 1];
      v = fminf(v, RAW[ey][ex + 1]);
      v = fminf(v, RAW[ey + 2][ex + 1]);
      v = fminf(v, RAW[ey + 1][ex]);
      v = fminf(v, RAW[ey + 1][ex + 2]);
    }
    ER[ey][ex] = v;
  }
  __syncthreads();

  int ox = tid & 63;
  int oyb = tid >> 6;
  float mn = 3.4e38f, mx = -3.4e38f;
#pragma unroll
  for (int k = 0; k < 4; k++) {
    int oy = oyb + 4 * k;
    float v = ER[oy + 1][ox + 1];
    v = fmaxf(v, ER[oy][ox + 1]);
    v = fmaxf(v, ER[oy + 2][ox + 1]);
    v = fmaxf(v, ER[oy + 1][ox]);
    v = fmaxf(v, ER[oy + 1][ox + 2]);
    int gy = gy0 + 2 + oy, gx = gx0 + 2 + ox;
    op[((unsigned)gy << 10) + (unsigned)gx] = v;
    mn = fminf(mn, v);
    mx = fmaxf(mx, v);
  }
#pragma unroll
  for (int o = 16; o; o >>= 1) {
    mn = fminf(mn, __shfl_down_sync(0xffffffffu, mn, o));
    mx = fmaxf(mx, __shfl_down_sync(0xffffffffu, mx, o));
  }
  int w = tid >> 5;
  if ((tid & 31) == 0) { smn[w] = mn; smx[w] = mx; }
  __syncthreads();
  if (tid == 0) {
    for (int i = 1; i < 8; i++) { mn = fminf(mn, smn[i]); mx = fmaxf(mx, smx[i]); }
    unsigned t = s >> 2;
    atomicMin(&g_red[t * 2u],     __float_as_uint(mn));
    atomicMax(&g_red[t * 2u + 1], __float_as_uint(mx));
  }
}

// ---------------------------------------------------------------------------
// async persistent propagation. Tile 128x80: 8 warps x KR=10 rows, 4 cols/lane
// ---------------------------------------------------------------------------
#define TW 128
#define KR 10
#define TH 80
#define RSM 8              // halo / max steps per round
#define HX 8
#define IW (TW - 2 * HX)   // 112
#define IH (TH - 2 * RSM)  // 64  (16 * 64 = 1024 exact)
#define NXT 10
#define NYT 16
#define NTILE (NXT * NYT * 8)   // 1280
#define NBLK 444           // 148 SMs x 3 blocks co-resident
#define NR 19              // 18 x 8 + 1 x 6 = 150 steps

__device__ __forceinline__ void gsync() {
  __threadfence();
  __syncthreads();
  if (threadIdx.x == 0) {
    volatile unsigned* vg = &g_bar_gen;
    unsigned gen = *vg;
    if (atomicAdd(&g_bar_cnt, 1u) == NBLK - 1u) {
      atomicExch(&g_bar_cnt, 0u);
      __threadfence();
      *vg = gen + 1u;
    } else {
      while (*vg == gen) { }
      __threadfence();
    }
  }
  __syncthreads();
}

__global__ void __launch_bounds__(256, 3) k_prop_all(float* __restrict__ out) {
  __shared__ int4 Bex[2][2][8][32];   // [parity][top/bot][warp][lane]
  __shared__ unsigned long long sredu[8];
  __shared__ int sredi[8];
  __shared__ int sact;
  int lane = threadIdx.x & 31;
  int w    = threadIdx.x >> 5;
  int k0   = w * KR;

  int nsg = 0;
  for (int rnd = 0; rnd < NR; rnd++) {
    int steps = (rnd == NR - 1) ? 6 : RSM;
    int* __restrict__ dst = (rnd & 1) ? g_labB : g_labA;
    const int* __restrict__ src = (rnd & 1) ? g_labA : g_labB; // rnd>=1 only

    for (int kk = 0; kk < 3; kk++) {
      unsigned t = blockIdx.x + (unsigned)kk * NBLK;
      if (t >= NTILE) break;
      unsigned s  = t / (NXT * NYT);
      unsigned rr = t - s * (NXT * NYT);
      unsigned ty = rr / NXT;
      unsigned tx = rr - ty * NXT;
      unsigned* myw = &g_tw[s][ty][tx];

      int act = 1;
      if (rnd > 0) {
        // acquire-wait on 9 cone neighbors' done >= rnd; gather chg bits
        if (w == 0) {
          int a = 0;
          if (lane < 9) {
            int yy = (int)ty + lane / 3 - 1;
            int xx = (int)tx + lane % 3 - 1;
            if (yy >= 0 && yy < NYT && xx >= 0 && xx < NXT) {
              const unsigned* pw = &g_tw[s][yy][xx];
              unsigned v = ld_acq(pw);
              while ((v >> 20) < (unsigned)rnd) { __nanosleep(64); v = ld_acq(pw); }
              a = (int)((v >> (rnd - 1)) & 1u);
            }
          }
          unsigned m = __ballot_sync(0xffffffffu, a != 0);
          if (lane == 0) sact = (m != 0u) ? 1 : 0;
        }
        __syncthreads();
        act = sact;
        __syncthreads();
      }

      if (!act) {   // fixed tile: identical in both buffers, zero work
        if (threadIdx.x == 0) {
          unsigned old = __ldcg(myw) & 0xFFFFFu;   // chg bits (bit rnd stays 0)
          st_rel(myw, (((unsigned)rnd + 1u) << 20) | old);
        }
        continue;
      }

      unsigned base = s << 20;
      int gx0 = (int)tx * IW - HX;
      int gy0 = (int)ty * IH - RSM;
      int gx  = gx0 + 4 * lane;           // multiple of 4 -> int4 aligned
      bool xin = (gx >= 0) && (gx <= 1020);
      bool xst = xin && (lane >= 2) && (lane <= 29);

      int c0[KR], c1[KR], c2[KR], c3[KR];

      if (rnd == 0) {
        // fused threshold: labels from opened floats (still live in g_labB)
        unsigned tt = s >> 2;
        float mnv = __uint_as_float(g_red[tt * 2u]);
        float mxv = __uint_as_float(g_red[tt * 2u + 1]);
        float dv  = __fadd_rn(__fsub_rn(mxv, mnv), 1e-10f);
        const float* __restrict__ opf = ((const float*)g_labB) + base;
        unsigned lbase = (s & 3u) << 20;
#pragma unroll
        for (int j = 0; j < KR; j++) {
          int gy = gy0 + k0 + j;
          int l0 = 0, l1 = 0, l2 = 0, l3 = 0;
          if (xin && (unsigned)gy < 1024u) {
            float4 f = *(const float4*)(opf + (((unsigned)gy) << 10) + (unsigned)gx);
            unsigned li = lbase + (((unsigned)gy) << 10) + (unsigned)gx;
            if (__fdiv_rn(__fsub_rn(f.x, mnv), dv) >= 0.5f) l0 = (int)(li + 1u);
            if (__fdiv_rn(__fsub_rn(f.y, mnv), dv) >= 0.5f) l1 = (int)(li + 2u);
            if (__fdiv_rn(__fsub_rn(f.z, mnv), dv) >= 0.5f) l2 = (int)(li + 3u);
            if (__fdiv_rn(__fsub_rn(f.w, mnv), dv) >= 0.5f) l3 = (int)(li + 4u);
          }
          c0[j] = l0; c1[j] = l1; c2[j] = l2; c3[j] = l3;
        }
      } else {
#pragma unroll
        for (int j = 0; j < KR; j++) {
          int gy = gy0 + k0 + j;
          int4 v = make_int4(0, 0, 0, 0);
          if (xin && (unsigned)gy < 1024u)
            v = __ldcg((const int4*)(src + base + (((unsigned)gy) << 10) + (unsigned)gx));
          c0[j] = v.x; c1[j] = v.y; c2[j] = v.z; c3[j] = v.w;
        }
      }

      unsigned f0 = 0u, f1 = 0u, f2 = 0u, f3 = 0u, validm = 0u;
#pragma unroll
      for (int j = 0; j < KR; j++) {
        f0 |= (c0[j] != 0 ? 1u : 0u) << j;
        f1 |= (c1[j] != 0 ? 1u : 0u) << j;
        f2 |= (c2[j] != 0 ? 1u : 0u) << j;
        f3 |= (c3[j] != 0 ? 1u : 0u) << j;
        int row = k0 + j;
        int gy = gy0 + row;
        if (xst && row >= RSM && row < TH - RSM && (unsigned)gy < 1024u)
          validm |= 1u << j;
      }

      if (rnd == 0 && s >= 4u) {          // numSg on interior px of lab
#pragma unroll
        for (int j = 0; j < KR; j++)
          if ((validm >> j) & 1u)
            nsg += ((f0 >> j) & 1) + ((f1 >> j) & 1) + ((f2 >> j) & 1) + ((f3 >> j) & 1);
      }

      for (int it = 0; it < steps; it++) {
        int pp = it & 1;
        Bex[pp][0][w][lane] = make_int4(c0[0], c1[0], c2[0], c3[0]);
        Bex[pp][1][w][lane] = make_int4(c0[KR - 1], c1[KR - 1], c2[KR - 1], c3[KR - 1]);
        __syncthreads();
        int4 ab = (w > 0) ? Bex[pp][1][w - 1][lane] : make_int4(0, 0, 0, 0);
        int4 bl = (w < 7) ? Bex[pp][0][w + 1][lane] : make_int4(0, 0, 0, 0);

        int a0 = ab.x, a1 = ab.y, a2 = ab.z, a3 = ab.w;
        int b0 = c0[0], b1 = c1[0], b2 = c2[0], b3 = c3[0];
#pragma unroll
        for (int j = 0; j < KR; j++) {
          int t0 = (j < KR - 1) ? c0[j + 1] : bl.x;
          int t1 = (j < KR - 1) ? c1[j + 1] : bl.y;
          int t2 = (j < KR - 1) ? c2[j + 1] : bl.z;
          int t3 = (j < KR - 1) ? c3[j + 1] : bl.w;
          int v0 = max3i(a0, b0, t0);
          int v1 = max3i(a1, b1, t1);
          int v2 = max3i(a2, b2, t2);
          int v3 = max3i(a3, b3, t3);
          // lane-edge shfl garbage stays in the discarded halo
          int lft = __shfl_up_sync(0xffffffffu, v3, 1);
          int rgt = __shfl_down_sync(0xffffffffu, v0, 1);
          c0[j] = ((f0 >> j) & 1u) ? max3i(lft, v0, v1) : 0;
          c1[j] = ((f1 >> j) & 1u) ? max3i(v0, v1, v2) : 0;
          c2[j] = ((f2 >> j) & 1u) ? max3i(v1, v2, v3) : 0;
          c3[j] = ((f3 >> j) & 1u) ? max3i(v2, v3, rgt) : 0;
          a0 = b0; a1 = b1; a2 = b2; a3 = b3;
          b0 = t0; b1 = t1; b2 = t2; b3 = t3;
        }
      }

      // store interior + 64-bit label sum (monotone change detector)
      unsigned long long psum = 0ull;
#pragma unroll
      for (int j = 0; j < KR; j++) {
        if (!((validm >> j) & 1u)) continue;
        int gy = gy0 + k0 + j;
        unsigned off = base + (((unsigned)gy) << 10) + (unsigned)gx;
        __stcg((int4*)(dst + off), make_int4(c0[j], c1[j], c2[j], c3[j]));
        psum += (unsigned long long)(unsigned)(c0[j] + c1[j] + c2[j] + c3[j]);
      }
#pragma unroll
      for (int o = 16; o; o >>= 1)
        psum += __shfl_down_sync(0xffffffffu, psum, o);
      if (lane == 0) sredu[w] = psum;
      __syncthreads();   // also orders all stcg stores before the release below
      if (threadIdx.x == 0) {
        unsigned long long tot = 0ull;
        for (int i = 0; i < 8; i++) tot += sredu[i];
        int tchg = (rnd == 0) ? 1 : (tot != __ldcg(&g_tsum[s][ty][tx]) ? 1 : 0);
        __stcg(&g_tsum[s][ty][tx], tot);
        unsigned old = (rnd == 0) ? 0u : (__ldcg(myw) & 0xFFFFFu);
        st_rel(myw, (((unsigned)rnd + 1u) << 20) | old | ((unsigned)tchg << rnd));
      }
      __syncthreads();
    }

    if (rnd == 0) {                       // block-reduce numSg once
#pragma unroll
      for (int o = 16; o; o >>= 1) nsg += __shfl_down_sync(0xffffffffu, nsg, o);
      if (lane == 0) sredi[w] = nsg;
      __syncthreads();
      if (threadIdx.x == 0) {
        int acc = 0;
        for (int i = 0; i < 8; i++) acc += sredi[i];
        if (acc) atomicAdd(&g_cnt[2], (unsigned)acc);
      }
      __syncthreads();
    }
  }

  gsync();  // all tiles through all 19 rounds; final field complete

  // ---- fused distinct count: v present iff px (v-1) holds label v ----
  const int* __restrict__ fin = g_labA;   // round 18 (even) output; skipped
                                          // tiles identical in both buffers
  int cnt0 = 0, cnt1 = 0, zer0 = 0, zer1 = 0;
  for (unsigned q = blockIdx.x * 256u + threadIdx.x; q < NPIX / 4u; q += NBLK * 256u) {
    unsigned idx = q * 4u;
    int4 v = __ldcg((const int4*)(fin + idx));
    int wt = (int)(idx & 0x3FFFFFu);
    int m = (v.x == wt + 1) + (v.y == wt + 2) + (v.z == wt + 3) + (v.w == wt + 4);
    int z = (v.x == 0) | (v.y == 0) | (v.z == 0) | (v.w == 0);
    if (idx >> 22) { cnt1 += m; zer1 |= z; } else { cnt0 += m; zer0 |= z; }
  }
#pragma unroll
  for (int o = 16; o; o >>= 1) {
    cnt0 += __shfl_down_sync(0xffffffffu, cnt0, o);
    cnt1 += __shfl_down_sync(0xffffffffu, cnt1, o);
    zer0 |= __shfl_down_sync(0xffffffffu, zer0, o);
    zer1 |= __shfl_down_sync(0xffffffffu, zer1, o);
  }
  __syncthreads();
  if (lane == 0) sredi[w] = cnt0;
  __syncthreads();
  if (threadIdx.x == 0) {
    int a = 0; for (int i = 0; i < 8; i++) a += sredi[i];
    if (a) atomicAdd(&g_cnt[0], (unsigned)a);
  }
  __syncthreads();
  if (lane == 0) sredi[w] = cnt1;
  __syncthreads();
  if (threadIdx.x == 0) {
    int a = 0; for (int i = 0; i < 8; i++) a += sredi[i];
    if (a) atomicAdd(&g_cnt[1], (unsigned)a);
  }
  if (lane == 0) {
    if (zer0) atomicOr(&g_zf[0], 1u);
    if (zer1) atomicOr(&g_zf[1], 1u);
  }

  gsync();  // all counts visible

  // ---- fused final scalar ----
  if (blockIdx.x == 0 && threadIdx.x == 0) {
    int c0 = (int)__ldcg(&g_cnt[0]) + ((__ldcg(&g_zf[0]) && __ldcg(&fin[0]) != 1) ? 1 : 0);
    int c1 = (int)__ldcg(&g_cnt[1]) + ((__ldcg(&g_zf[1]) && __ldcg(&fin[4u << 20]) != 1) ? 1 : 0);
    float ccs  = (float)c0;
    float ccsg = (float)c1;
    float ns   = (float)__ldcg(&g_cnt[2]);
    out[0] = __fdiv_rn(fabsf(__fsub_rn(ccsg, ccs)), ns);
  }
}

// ---------------------------------------------------------------------------
extern "C" void kernel_launch(void* const* d_in, const int* in_sizes, int n_in,
                              void* d_out, int out_size) {
  const float* img = (const float*)d_in[0];
  const float* lab = (const float*)d_in[1];
  float* out = (float*)d_out;

  k_init<<<1, 256>>>();
  k_open<<<dim3(1024 / OX, 1024 / OY, 8), 256>>>(img, lab);
  k_prop_all<<<NBLK, 256>>>(out);
}